// round 13
// baseline (speedup 1.0000x reference)
#include <cuda_runtime.h>
#include <cuda_bf16.h>
#include <math.h>
#include <stdint.h>

// Problem constants
#define NB   2
#define NS   2048
#define ND   1024
#define NH   16
#define NHD  64
#define NBH  (NB*NH)       // 32
#define NM   (NB*NS)       // 4096
#define OUT_ELEMS  (NB*NS*ND)                        // 4,194,304
#define ATTN_ELEMS ((long long)NBH*(long long)NS*NS) // 134,217,728

#define NEG_INF __int_as_float(0xff800000)

// ---- scratch (device globals; no runtime allocation allowed) ----
__device__ float g_attn_scratch[134217728]; // fallback if out buffer excludes attn
__device__ int   g_mask_is_u8;
// bf16 split operands (separate buffers so Q/K/V pipelines are independent)
__device__ __nv_bfloat16 g_a0h[NM * ND], g_a0l[NM * ND];   // query split / ctx split
__device__ __nv_bfloat16 g_a1h[NM * ND], g_a1l[NM * ND];   // key split
__device__ __nv_bfloat16 g_a2h[NM * ND], g_a2l[NM * ND];   // value split
__device__ __nv_bfloat16 g_w0h[ND * ND], g_w0l[ND * ND];   // Wq^T
__device__ __nv_bfloat16 g_w1h[ND * ND], g_w1l[ND * ND];   // Wk^T
__device__ __nv_bfloat16 g_w2h[ND * ND], g_w2l[ND * ND];   // Wv^T
__device__ __nv_bfloat16 g_w3h[ND * ND], g_w3l[ND * ND];   // Wo^T
__device__ __nv_bfloat16 g_qh[NBH * NS * NHD], g_ql[NBH * NS * NHD];
__device__ __nv_bfloat16 g_kh[NBH * NS * NHD], g_kl[NBH * NS * NHD];
__device__ __nv_bfloat16 g_vh[NBH * NS * NHD], g_vl[NBH * NS * NHD];

// ---------------------------------------------------------------------------
__global__ void detect_mask_kernel(const unsigned char* __restrict__ m) {
    g_mask_is_u8 = (m[1] != 0) ? 1 : 0;
}

// ---------------------------------------------------------------------------
// helpers
// ---------------------------------------------------------------------------
__device__ __forceinline__ void split2(float x0, float x1,
                                       unsigned& hi, unsigned& lo) {
    __nv_bfloat16 h0 = __float2bfloat16(x0);
    __nv_bfloat16 h1 = __float2bfloat16(x1);
    __nv_bfloat162 hp = __halves2bfloat162(h0, h1);
    hi = *reinterpret_cast<unsigned*>(&hp);
    float l0 = x0 - __bfloat162float(h0);
    float l1 = x1 - __bfloat162float(h1);
    __nv_bfloat162 lp = __floats2bfloat162_rn(l0, l1);
    lo = *reinterpret_cast<unsigned*>(&lp);
}

__device__ __forceinline__ void mma16(float* c, const unsigned* a, const unsigned* b) {
    asm volatile(
        "mma.sync.aligned.m16n8k16.row.col.f32.bf16.bf16.f32 "
        "{%0,%1,%2,%3}, {%4,%5,%6,%7}, {%8,%9}, {%0,%1,%2,%3};"
        : "+f"(c[0]), "+f"(c[1]), "+f"(c[2]), "+f"(c[3])
        : "r"(a[0]), "r"(a[1]), "r"(a[2]), "r"(a[3]), "r"(b[0]), "r"(b[1]));
}

__device__ __forceinline__ uint32_t smem_u32(const void* p) {
    uint32_t a;
    asm("{ .reg .u64 t; cvta.to.shared.u64 t, %1; cvt.u32.u64 %0, t; }"
        : "=r"(a) : "l"(p));
    return a;
}

__device__ __forceinline__ void ldsm_x4(unsigned& r0, unsigned& r1,
                                        unsigned& r2, unsigned& r3, uint32_t a) {
    asm volatile("ldmatrix.sync.aligned.m8n8.x4.shared.b16 {%0,%1,%2,%3}, [%4];"
                 : "=r"(r0), "=r"(r1), "=r"(r2), "=r"(r3) : "r"(a));
}
__device__ __forceinline__ void ldsm_x4_t(unsigned& r0, unsigned& r1,
                                          unsigned& r2, unsigned& r3, uint32_t a) {
    asm volatile("ldmatrix.sync.aligned.m8n8.x4.trans.shared.b16 {%0,%1,%2,%3}, [%4];"
                 : "=r"(r0), "=r"(r1), "=r"(r2), "=r"(r3) : "r"(a));
}

__device__ __forceinline__ void cp16(uint32_t dst, const void* src) {
    asm volatile("cp.async.cg.shared.global [%0], [%1], 16;"
                 :: "r"(dst), "l"(src));
}
#define CP_COMMIT() asm volatile("cp.async.commit_group;" ::: "memory")
#define CP_WAIT1()  asm volatile("cp.async.wait_group 1;" ::: "memory")
#define CP_WAIT0()  asm volatile("cp.async.wait_group 0;" ::: "memory")

// ---------------------------------------------------------------------------
// Prep kernels — merged across the 3 inputs / 4 weights (blockIdx.z selects)
// ---------------------------------------------------------------------------
__global__ void split3_kernel(const float* __restrict__ X0,
                              const float* __restrict__ X1,
                              const float* __restrict__ X2,
                              __nv_bfloat16* __restrict__ H0, __nv_bfloat16* __restrict__ L0,
                              __nv_bfloat16* __restrict__ H1, __nv_bfloat16* __restrict__ L1,
                              __nv_bfloat16* __restrict__ H2, __nv_bfloat16* __restrict__ L2,
                              int n4)
{
    int idx = blockIdx.x * blockDim.x + threadIdx.x;
    if (idx >= n4) return;
    const int z = blockIdx.z;
    const float* X = (z == 0) ? X0 : (z == 1) ? X1 : X2;
    __nv_bfloat16* hi = (z == 0) ? H0 : (z == 1) ? H1 : H2;
    __nv_bfloat16* lo = (z == 0) ? L0 : (z == 1) ? L1 : L2;
    float4 v = ((const float4*)X)[idx];
    unsigned h01, l01, h23, l23;
    split2(v.x, v.y, h01, l01);
    split2(v.z, v.w, h23, l23);
    ((uint2*)hi)[idx] = make_uint2(h01, h23);
    ((uint2*)lo)[idx] = make_uint2(l01, l23);
}

__global__ void transpose4_kernel(const float* __restrict__ W0,
                                  const float* __restrict__ W1,
                                  const float* __restrict__ W2,
                                  const float* __restrict__ W3,
                                  __nv_bfloat16* __restrict__ T0h, __nv_bfloat16* __restrict__ T0l,
                                  __nv_bfloat16* __restrict__ T1h, __nv_bfloat16* __restrict__ T1l,
                                  __nv_bfloat16* __restrict__ T2h, __nv_bfloat16* __restrict__ T2l,
                                  __nv_bfloat16* __restrict__ T3h, __nv_bfloat16* __restrict__ T3l)
{
    __shared__ float ts[32][33];
    const int z = blockIdx.z;
    const float* W = (z == 0) ? W0 : (z == 1) ? W1 : (z == 2) ? W2 : W3;
    __nv_bfloat16* Th = (z == 0) ? T0h : (z == 1) ? T1h : (z == 2) ? T2h : T3h;
    __nv_bfloat16* Tl = (z == 0) ? T0l : (z == 1) ? T1l : (z == 2) ? T2l : T3l;

    int n0 = blockIdx.x * 32, k0 = blockIdx.y * 32;
    int tx = threadIdx.x, ty = threadIdx.y;  // (32, 8)
    #pragma unroll
    for (int i = 0; i < 4; i++)
        ts[ty * 4 + i][tx] = W[(size_t)(k0 + ty * 4 + i) * ND + n0 + tx];
    __syncthreads();
    #pragma unroll
    for (int i = 0; i < 4; i++) {
        int nl = ty * 4 + i;
        float v = ts[tx][nl];
        __nv_bfloat16 h = __float2bfloat16(v);
        float l = v - __bfloat162float(h);
        size_t o = (size_t)(n0 + nl) * ND + k0 + tx;
        Th[o] = h;
        Tl[o] = __float2bfloat16(l);
    }
}

// ---------------------------------------------------------------------------
// Projection GEMM core (device inline). cp.async 2-stage ring, one barrier
// per k-tile. 128x128 block, ktile 32, 8 warps (2m x 4n), 3xBF16.
// ---------------------------------------------------------------------------
#define PITCH 80
#define TILE_B (128 * PITCH)      // 10240
#define STG    (4 * TILE_B)       // 40960 per stage
#define PROJ_DSMEM (2 * STG)      // 81920

__device__ __forceinline__ void proj_core(
    char* sm,
    const __nv_bfloat16* __restrict__ Ahi, const __nv_bfloat16* __restrict__ Alo,
    const __nv_bfloat16* __restrict__ Bhi, const __nv_bfloat16* __restrict__ Blo,
    const float* __restrict__ bias,
    float* __restrict__ Cf,
    __nv_bfloat16* __restrict__ Chi, __nv_bfloat16* __restrict__ Clo,
    int mode, int row0, int col0)
{
    const int tid  = threadIdx.x;
    const int warp = tid >> 5, lane = tid & 31;
    const int gid  = lane >> 2, tig = lane & 3;
    const int wm   = (warp & 1) * 64;
    const int wn   = (warp >> 1) * 32;

    const uint32_t sb = smem_u32(sm);
    const int q = lane >> 3, rr = lane & 7;
    const uint32_t aOff = (uint32_t)((wm + (q & 1) * 8 + rr) * PITCH + (q >> 1) * 16);
    const uint32_t bOff = 2u * TILE_B +
                          (uint32_t)((wn + (q >> 1) * 8 + rr) * PITCH + (q & 1) * 16);
    const int cr0 = tid >> 2,           cc0 = tid & 3;
    const int cr1 = (256 + tid) >> 2,   cc1 = (256 + tid) & 3;

    float acc[4][4][4] = {};

    #define PJ_ISSUE(stage, k0v) do {                                            \
        const uint32_t stg_ = sb + (uint32_t)((stage) * STG);                    \
        uint32_t d0 = stg_ + (uint32_t)(cr0 * PITCH + cc0 * 16);                 \
        size_t ga0 = (size_t)(row0 + cr0) * ND + (k0v) + cc0 * 8;                \
        size_t gb0 = (size_t)(col0 + cr0) * ND + (k0v) + cc0 * 8;                \
        cp16(d0, Ahi + ga0);              cp16(d0 + TILE_B, Alo + ga0);          \
        cp16(d0 + 2*TILE_B, Bhi + gb0);   cp16(d0 + 3*TILE_B, Blo + gb0);        \
        uint32_t d1 = stg_ + (uint32_t)(cr1 * PITCH + cc1 * 16);                 \
        size_t ga1 = (size_t)(row0 + cr1) * ND + (k0v) + cc1 * 8;                \
        size_t gb1 = (size_t)(col0 + cr1) * ND + (k0v) + cc1 * 8;                \
        cp16(d1, Ahi + ga1);              cp16(d1 + TILE_B, Alo + ga1);          \
        cp16(d1 + 2*TILE_B, Bhi + gb1);   cp16(d1 + 3*TILE_B, Blo + gb1);        \
        CP_COMMIT();                                                             \
    } while (0)

    PJ_ISSUE(0, 0);

    #pragma unroll 1
    for (int kt = 0; kt < 32; kt++) {
        CP_WAIT0();
        __syncthreads();
        if (kt + 1 < 32)
            PJ_ISSUE((kt + 1) & 1, (kt + 1) * 32);

        const uint32_t stb = sb + (uint32_t)((kt & 1) * STG);
        const uint32_t aA = stb + aOff, bA = stb + bOff;

        #pragma unroll
        for (int ks = 0; ks < 2; ks++) {
            const uint32_t kb = ks * 32;
            unsigned ah[4][4], al[4][4], bx[4][2];
            #pragma unroll
            for (int mt = 0; mt < 4; mt++)
                ldsm_x4(ah[mt][0], ah[mt][1], ah[mt][2], ah[mt][3],
                        aA + mt * 16 * PITCH + kb);
            #pragma unroll
            for (int n2 = 0; n2 < 2; n2++)
                ldsm_x4(bx[n2*2][0], bx[n2*2][1], bx[n2*2+1][0], bx[n2*2+1][1],
                        bA + n2 * 16 * PITCH + kb);
            #pragma unroll
            for (int mt = 0; mt < 4; mt++)
                #pragma unroll
                for (int nt = 0; nt < 4; nt++)
                    mma16(acc[mt][nt], ah[mt], bx[nt]);     // hi*hi
            #pragma unroll
            for (int mt = 0; mt < 4; mt++)
                ldsm_x4(al[mt][0], al[mt][1], al[mt][2], al[mt][3],
                        aA + TILE_B + mt * 16 * PITCH + kb);
            #pragma unroll
            for (int mt = 0; mt < 4; mt++)
                #pragma unroll
                for (int nt = 0; nt < 4; nt++)
                    mma16(acc[mt][nt], al[mt], bx[nt]);     // lo*hi
            #pragma unroll
            for (int n2 = 0; n2 < 2; n2++)
                ldsm_x4(bx[n2*2][0], bx[n2*2][1], bx[n2*2+1][0], bx[n2*2+1][1],
                        bA + TILE_B + n2 * 16 * PITCH + kb);
            #pragma unroll
            for (int mt = 0; mt < 4; mt++)
                #pragma unroll
                for (int nt = 0; nt < 4; nt++)
                    mma16(acc[mt][nt], ah[mt], bx[nt]);     // hi*lo
        }
    }

    #pragma unroll
    for (int mt = 0; mt < 4; mt++) {
        #pragma unroll
        for (int nt = 0; nt < 4; nt++) {
            int n = col0 + wn + nt * 8 + tig * 2;
            float b0 = bias[n], b1 = bias[n + 1];
            #pragma unroll
            for (int h2 = 0; h2 < 2; h2++) {
                int m = row0 + wm + mt * 16 + gid + h2 * 8;
                float c0 = acc[mt][nt][h2 * 2]     + b0;
                float c1 = acc[mt][nt][h2 * 2 + 1] + b1;
                if (mode == 1) {
                    int b = m >> 11, s = m & (NS - 1), hh = n >> 6, d = n & 63;
                    size_t o = (((size_t)(b * NH + hh)) * NS + s) * NHD + d;
                    unsigned hv, lv;
                    split2(c0, c1, hv, lv);
                    *(unsigned*)&Chi[o] = hv;
                    *(unsigned*)&Clo[o] = lv;
                } else {
                    *(float2*)&Cf[(size_t)m * ND + n] = make_float2(c0, c1);
                }
            }
        }
    }
    #undef PJ_ISSUE
}

// merged QKV projection: gridDim.z = 3 selects the pipeline
__global__ void __launch_bounds__(256, 2)
proj_qkv_kernel(const __nv_bfloat16* __restrict__ A0h, const __nv_bfloat16* __restrict__ A0l,
                const __nv_bfloat16* __restrict__ A1h, const __nv_bfloat16* __restrict__ A1l,
                const __nv_bfloat16* __restrict__ A2h, const __nv_bfloat16* __restrict__ A2l,
                const __nv_bfloat16* __restrict__ B0h, const __nv_bfloat16* __restrict__ B0l,
                const __nv_bfloat16* __restrict__ B1h, const __nv_bfloat16* __restrict__ B1l,
                const __nv_bfloat16* __restrict__ B2h, const __nv_bfloat16* __restrict__ B2l,
                const float* __restrict__ bq, const float* __restrict__ bk,
                const float* __restrict__ bv,
                __nv_bfloat16* __restrict__ qh, __nv_bfloat16* __restrict__ ql,
                __nv_bfloat16* __restrict__ kh, __nv_bfloat16* __restrict__ kl,
                __nv_bfloat16* __restrict__ vh, __nv_bfloat16* __restrict__ vl)
{
    extern __shared__ __align__(16) char sm[];
    const int z = blockIdx.z;
    const __nv_bfloat16* Ahi = (z == 0) ? A0h : (z == 1) ? A1h : A2h;
    const __nv_bfloat16* Alo = (z == 0) ? A0l : (z == 1) ? A1l : A2l;
    const __nv_bfloat16* Bhi = (z == 0) ? B0h : (z == 1) ? B1h : B2h;
    const __nv_bfloat16* Blo = (z == 0) ? B0l : (z == 1) ? B1l : B2l;
    const float* bias = (z == 0) ? bq : (z == 1) ? bk : bv;
    __nv_bfloat16* Chi = (z == 0) ? qh : (z == 1) ? kh : vh;
    __nv_bfloat16* Clo = (z == 0) ? ql : (z == 1) ? kl : vl;
    proj_core(sm, Ahi, Alo, Bhi, Blo, bias, nullptr, Chi, Clo, 1,
              blockIdx.y * 128, blockIdx.x * 128);
}

// output projection (fp32 out)
__global__ void __launch_bounds__(256, 2)
proj_out_kernel(const __nv_bfloat16* __restrict__ Ahi, const __nv_bfloat16* __restrict__ Alo,
                const __nv_bfloat16* __restrict__ Bhi, const __nv_bfloat16* __restrict__ Blo,
                const float* __restrict__ bias, float* __restrict__ Cf)
{
    extern __shared__ __align__(16) char sm[];
    proj_core(sm, Ahi, Alo, Bhi, Blo, bias, Cf, nullptr, nullptr, 0,
              blockIdx.y * 128, blockIdx.x * 128);
}

// ---------------------------------------------------------------------------
// Scores: attn = mask ? (Q.K)*scale : -inf. Mask tile staged through smem
// (coalesced uint4) to kill the 4x sector amplification of scattered 2B loads.
// grid = (kt=16, qt=16, bh=32)
// ---------------------------------------------------------------------------
__global__ void __launch_bounds__(256, 2)
score_mma_kernel(const __nv_bfloat16* __restrict__ qh_g,
                 const __nv_bfloat16* __restrict__ ql_g,
                 const __nv_bfloat16* __restrict__ kh_g,
                 const __nv_bfloat16* __restrict__ kl_g,
                 const unsigned char* __restrict__ mask8,
                 float* __restrict__ attn)
{
    extern __shared__ __align__(16) char sm[];

    const int tid  = threadIdx.x;
    const int warp = tid >> 5, lane = tid & 31;
    const int gid  = lane >> 2, tig = lane & 3;
    const int wm   = (warp & 1) * 64;
    const int wn   = (warp >> 1) * 32;
    const int kt = blockIdx.x, qt = blockIdx.y, bh_i = blockIdx.z;

    const size_t hb = (size_t)bh_i * NS * NHD;
    const uint32_t sb = smem_u32(sm);
    const int q = lane >> 3, rr = lane & 7;
    const uint32_t aOff = (uint32_t)((wm + (q & 1) * 8 + rr) * PITCH + (q >> 1) * 16);
    const uint32_t bOff = 2u * TILE_B +
                          (uint32_t)((wn + (q >> 1) * 8 + rr) * PITCH + (q & 1) * 16);
    const int cr0 = tid >> 2,         cc0 = tid & 3;
    const int cr1 = (256 + tid) >> 2, cc1 = (256 + tid) & 3;

    float acc[4][4][4] = {};

    #define SC_ISSUE(stage, d0v)  do {                                          \
        const uint32_t stg_ = sb + (uint32_t)((stage) * STG);                   \
        uint32_t da0 = stg_ + (uint32_t)(cr0 * PITCH + cc0 * 16);               \
        size_t gq0 = hb + (size_t)(qt * 128 + cr0) * NHD + (d0v) + cc0 * 8;     \
        size_t gk0 = hb + (size_t)(kt * 128 + cr0) * NHD + (d0v) + cc0 * 8;     \
        cp16(da0, qh_g + gq0);             cp16(da0 + TILE_B, ql_g + gq0);      \
        cp16(da0 + 2*TILE_B, kh_g + gk0);  cp16(da0 + 3*TILE_B, kl_g + gk0);    \
        uint32_t da1 = stg_ + (uint32_t)(cr1 * PITCH + cc1 * 16);               \
        size_t gq1 = hb + (size_t)(qt * 128 + cr1) * NHD + (d0v) + cc1 * 8;     \
        size_t gk1 = hb + (size_t)(kt * 128 + cr1) * NHD + (d0v) + cc1 * 8;     \
        cp16(da1, qh_g + gq1);             cp16(da1 + TILE_B, ql_g + gq1);      \
        cp16(da1 + 2*TILE_B, kh_g + gk1);  cp16(da1 + 3*TILE_B, kl_g + gk1);    \
        CP_COMMIT();                                                            \
    } while (0)

    SC_ISSUE(0, 0);

    #pragma unroll
    for (int dt = 0; dt < 2; dt++) {
        CP_WAIT0();
        __syncthreads();
        if (dt + 1 < 2) SC_ISSUE(1, 32);

        const uint32_t stb = sb + (uint32_t)((dt & 1) * STG);
        const uint32_t aA = stb + aOff, bA = stb + bOff;

        #pragma unroll
        for (int ks = 0; ks < 2; ks++) {
            const uint32_t kb = ks * 32;
            unsigned ah[4][4], al[4][4], bx[4][2];
            #pragma unroll
            for (int mt = 0; mt < 4; mt++)
                ldsm_x4(ah[mt][0], ah[mt][1], ah[mt][2], ah[mt][3],
                        aA + mt * 16 * PITCH + kb);
            #pragma unroll
            for (int n2 = 0; n2 < 2; n2++)
                ldsm_x4(bx[n2*2][0], bx[n2*2][1], bx[n2*2+1][0], bx[n2*2+1][1],
                        bA + n2 * 16 * PITCH + kb);
            #pragma unroll
            for (int mt = 0; mt < 4; mt++)
                #pragma unroll
                for (int nt = 0; nt < 4; nt++)
                    mma16(acc[mt][nt], ah[mt], bx[nt]);
            #pragma unroll
            for (int mt = 0; mt < 4; mt++)
                ldsm_x4(al[mt][0], al[mt][1], al[mt][2], al[mt][3],
                        aA + TILE_B + mt * 16 * PITCH + kb);
            #pragma unroll
            for (int mt = 0; mt < 4; mt++)
                #pragma unroll
                for (int nt = 0; nt < 4; nt++)
                    mma16(acc[mt][nt], al[mt], bx[nt]);
            #pragma unroll
            for (int n2 = 0; n2 < 2; n2++)
                ldsm_x4(bx[n2*2][0], bx[n2*2][1], bx[n2*2+1][0], bx[n2*2+1][1],
                        bA + TILE_B + n2 * 16 * PITCH + kb);
            #pragma unroll
            for (int mt = 0; mt < 4; mt++)
                #pragma unroll
                for (int nt = 0; nt < 4; nt++)
                    mma16(acc[mt][nt], ah[mt], bx[nt]);
        }
    }

    // ---- stage mask tile into (dead) pipeline smem, coalesced ----
    const int use8 = g_mask_is_u8;
    __syncthreads();   // all warps done reading stage smem
    if (use8) {
        // 128 rows x 128 B = 1024 uint4 tasks, 4/thread
        #pragma unroll
        for (int i = 0; i < 4; i++) {
            int t = i * 256 + tid;
            int r = t >> 3, c16 = t & 7;
            *(uint4*)(sm + r * 128 + c16 * 16) =
                *(const uint4*)&mask8[(size_t)(qt * 128 + r) * NS + kt * 128 + c16 * 16];
        }
    } else {
        // int32: 128 rows x 512 B = 4096 uint4 tasks, 16/thread
        const unsigned char* m32 = mask8;
        #pragma unroll
        for (int i = 0; i < 16; i++) {
            int t = i * 256 + tid;
            int r = t >> 5, c16 = t & 31;
            *(uint4*)(sm + r * 512 + c16 * 16) =
                *(const uint4*)&m32[((size_t)(qt * 128 + r) * NS + kt * 128) * 4 + c16 * 16];
        }
    }
    __syncthreads();

    const float scale = 0.125f;

    #pragma unroll
    for (int mt = 0; mt < 4; mt++) {
        #pragma unroll
        for (int nt = 0; nt < 4; nt++) {
            int nl = wn + nt * 8 + tig * 2;            // local col
            int n  = kt * 128 + nl;
            #pragma unroll
            for (int h2 = 0; h2 < 2; h2++) {
                int ml = wm + mt * 16 + gid + h2 * 8;  // local row
                int m  = qt * 128 + ml;
                float c0 = acc[mt][nt][h2 * 2]     * scale;
                float c1 = acc[mt][nt][h2 * 2 + 1] * scale;
                bool m0, m1;
                if (use8) {
                    uchar2 mv = *(const uchar2*)(sm + ml * 128 + nl);
                    m0 = mv.x != 0; m1 = mv.y != 0;
                } else {
                    int2 mv = *(const int2*)(sm + ml * 512 + nl * 4);
                    m0 = mv.x != 0; m1 = mv.y != 0;
                }
                float2 o = make_float2(m0 ? c0 : NEG_INF, m1 ? c1 : NEG_INF);
                *(float2*)&attn[((size_t)bh_i * NS + m) * NS + n] = o;
            }
        }
    }
}

// ---------------------------------------------------------------------------
// Row softmax over 2048 elements, in place. (R8 proven)
// ---------------------------------------------------------------------------
__global__ void softmax_kernel(float* __restrict__ attn)
{
    const size_t row = blockIdx.x;
    float* p = attn + row * (size_t)NS;
    const int tid = threadIdx.x;

    float v[8];
    float mx = NEG_INF;
    #pragma unroll
    for (int i = 0; i < 8; i++) {
        v[i] = p[tid + i * 256];
        mx = fmaxf(mx, v[i]);
    }

    __shared__ float sh[8];
    #pragma unroll
    for (int o = 16; o > 0; o >>= 1)
        mx = fmaxf(mx, __shfl_xor_sync(0xffffffffu, mx, o));
    if ((tid & 31) == 0) sh[tid >> 5] = mx;
    __syncthreads();
    if (tid < 32) {
        float m2 = (tid < 8) ? sh[tid] : NEG_INF;
        #pragma unroll
        for (int o = 4; o > 0; o >>= 1)
            m2 = fmaxf(m2, __shfl_xor_sync(0xffffffffu, m2, o));
        if (tid == 0) sh[0] = m2;
    }
    __syncthreads();
    mx = sh[0];
    __syncthreads();

    float s = 0.0f;
    #pragma unroll
    for (int i = 0; i < 8; i++) {
        v[i] = __expf(v[i] - mx);
        s += v[i];
    }
    #pragma unroll
    for (int o = 16; o > 0; o >>= 1)
        s += __shfl_xor_sync(0xffffffffu, s, o);
    if ((tid & 31) == 0) sh[tid >> 5] = s;
    __syncthreads();
    if (tid < 32) {
        float s2 = (tid < 8) ? sh[tid] : 0.0f;
        #pragma unroll
        for (int o = 4; o > 0; o >>= 1)
            s2 += __shfl_xor_sync(0xffffffffu, s2, o);
        if (tid == 0) sh[0] = s2;
    }
    __syncthreads();
    const float inv = 1.0f / sh[0];

    #pragma unroll
    for (int i = 0; i < 8; i++)
        p[tid + i * 256] = v[i] * inv;
}

// ---------------------------------------------------------------------------
// PV: 64(q) x 64(d) block tiles for wave balance (1024 CTAs = 3.46 waves).
// 8 warps (2m x 4n), warp tile 32x16. P reg-prefetch + inline split;
// V cp.async ring. grid = (qt=32, bh=32). Math order identical to R8.
// ---------------------------------------------------------------------------
#define AP_TILE (64 * PITCH)       // 5120 per P tile (hi or lo)
#define VPITCH 144
#define VTILE_B (32 * VPITCH)      // 4608
#define VSTG    (2 * VTILE_B)      // 9216 (hi+lo)
#define VBASE   (2 * AP_TILE)      // after Ph, Pl

__global__ void __launch_bounds__(256, 2)
av_mma_kernel(const float* __restrict__ attn,
              const __nv_bfloat16* __restrict__ vh_g,
              const __nv_bfloat16* __restrict__ vl_g,
              __nv_bfloat16* __restrict__ Chi,
              __nv_bfloat16* __restrict__ Clo)
{
    __shared__ __align__(16) char sm[VBASE + 2 * VSTG];  // Ph | Pl | Vstg0 | Vstg1

    const int tid  = threadIdx.x;
    const int warp = tid >> 5, lane = tid & 31;
    const int gid  = lane >> 2, tig = lane & 3;
    const int wm   = (warp & 1) * 32;     // 2 m-groups of 32
    const int wn   = (warp >> 1) * 16;    // 4 n-groups of 16
    const int qt = blockIdx.x, bh_i = blockIdx.y;

    const size_t hb = (size_t)bh_i * NS * NHD;
    const float* prow = attn + ((size_t)bh_i * NS + qt * 64) * NS;

    const uint32_t sb = smem_u32(sm);
    const int q = lane >> 3, rr = lane & 7;
    const uint32_t aAddr = sb + (uint32_t)((wm + (q & 1) * 8 + rr) * PITCH + (q >> 1) * 16);
    const uint32_t vOff  = (uint32_t)(((q & 1) * 8 + rr) * VPITCH + (wn + (q >> 1) * 8) * 2);
    const int vr = tid >> 3, vc = tid & 7;

    float acc[2][2][4] = {};
    float4 pr[2];

    // prologue: V stage 0 + P regs tile 0
    {
        size_t gv = hb + (size_t)vr * NHD + vc * 8;
        uint32_t d = sb + VBASE + (uint32_t)(vr * VPITCH + vc * 16);
        cp16(d, vh_g + gv);
        cp16(d + VTILE_B, vl_g + gv);
        CP_COMMIT();
        #pragma unroll
        for (int i = 0; i < 2; i++) {
            int idx = i * 256 + tid;
            int r = idx >> 3, c4 = idx & 7;
            pr[i] = *(const float4*)&prow[(size_t)r * NS + c4 * 4];
        }
    }

    #pragma unroll 1
    for (int kt = 0; kt < 64; kt++) {
        if (kt + 1 < 64) {
            size_t gv = hb + (size_t)((kt + 1) * 32 + vr) * NHD + vc * 8;
            uint32_t d = sb + VBASE + (uint32_t)(((kt + 1) & 1) * VSTG + vr * VPITCH + vc * 16);
            cp16(d, vh_g + gv);
            cp16(d + VTILE_B, vl_g + gv);
            CP_COMMIT();
        }
        // STS P from regs (split inline)
        #pragma unroll
        for (int i = 0; i < 2; i++) {
            int idx = i * 256 + tid;
            int r = idx >> 3, c4 = idx & 7;
            unsigned h01, l01, h23, l23;
            split2(pr[i].x, pr[i].y, h01, l01);
            split2(pr[i].z, pr[i].w, h23, l23);
            uint32_t da = (uint32_t)(r * PITCH + c4 * 8);
            *(uint2*)(sm + da)           = make_uint2(h01, h23);
            *(uint2*)(sm + AP_TILE + da) = make_uint2(l01, l23);
        }
        // prefetch next P tile into regs (lands during mma)
        if (kt + 1 < 64) {
            const int k0n = (kt + 1) * 32;
            #pragma unroll
            for (int i = 0; i < 2; i++) {
                int idx = i * 256 + tid;
                int r = idx >> 3, c4 = idx & 7;
                pr[i] = *(const float4*)&prow[(size_t)r * NS + k0n + c4 * 4];
            }
            CP_WAIT1();
        } else {
            CP_WAIT0();
        }
        __syncthreads();

        const uint32_t vA = sb + VBASE + (uint32_t)((kt & 1) * VSTG) + vOff;

        #pragma unroll
        for (int ks = 0; ks < 2; ks++) {
            const uint32_t kb  = ks * 32;
            const uint32_t vkb = ks * 16 * VPITCH;
            unsigned ah[2][4], al[2][4], bx[2][2];
            #pragma unroll
            for (int mt = 0; mt < 2; mt++)
                ldsm_x4(ah[mt][0], ah[mt][1], ah[mt][2], ah[mt][3],
                        aAddr + mt * 16 * PITCH + kb);
            ldsm_x4_t(bx[0][0], bx[0][1], bx[1][0], bx[1][1], vA + vkb);
            #pragma unroll
            for (int mt = 0; mt < 2; mt++)
                #pragma unroll
                for (int nt = 0; nt < 2; nt++)
                    mma16(acc[mt][nt], ah[mt], bx[nt]);
            #pragma unroll
            for (int mt = 0; mt < 2; mt++)
                ldsm_x4(al[mt][0], al[mt][1], al[mt][2], al[mt][3],
                        aAddr + AP_TILE + mt * 16 * PITCH + kb);
            #pragma unroll
            for (int mt = 0; mt < 2; mt++)
                #pragma unroll
                for (int nt = 0; nt < 2; nt++)
                    mma16(acc[mt][nt], al[mt], bx[nt]);
            ldsm_x4_t(bx[0][0], bx[0][1], bx[1][0], bx[1][1], vA + VTILE_B + vkb);
            #pragma unroll
            for (int mt = 0; mt < 2; mt++)
                #pragma unroll
                for (int nt = 0; nt < 2; nt++)
                    mma16(acc[mt][nt], ah[mt], bx[nt]);
        }
        __syncthreads();
    }

    // epilogue: split ctx, write to out-proj A buffers [b*2048+s][h*64+d]
    const int b = bh_i >> 4, h = bh_i & 15;
    #pragma unroll
    for (int mt = 0; mt < 2; mt++) {
        #pragma unroll
        for (int nt = 0; nt < 2; nt++) {
            int n = wn + nt * 8 + tig * 2;
            #pragma unroll
            for (int h2 = 0; h2 < 2; h2++) {
                int s = qt * 64 + wm + mt * 16 + gid + h2 * 8;
                unsigned hv, lv;
                split2(acc[mt][nt][h2 * 2], acc[mt][nt][h2 * 2 + 1], hv, lv);
                size_t o = (size_t)(b * NS + s) * ND + h * NHD + n;
                *(unsigned*)&Chi[o] = hv;
                *(unsigned*)&Clo[o] = lv;
            }
        }
    }
}

// ---------------------------------------------------------------------------
extern "C" void kernel_launch(void* const* d_in, const int* in_sizes, int n_in,
                              void* d_out, int out_size)
{
    (void)in_sizes; (void)n_in;

    const float* query = (const float*)d_in[0];
    const float* key   = (const float*)d_in[1];
    const float* value = (const float*)d_in[2];
    const float* Wq    = (const float*)d_in[3];
    const float* bq    = (const float*)d_in[4];
    const float* Wk    = (const float*)d_in[5];
    const float* bk    = (const float*)d_in[6];
    const float* Wv    = (const float*)d_in[7];
    const float* bv    = (const float*)d_in[8];
    const float* Wo    = (const float*)d_in[9];
    const float* bo    = (const float*)d_in[10];
    const unsigned char* mask = (const unsigned char*)d_in[11];

    float* out = (float*)d_out;

    float* attn;
    __nv_bfloat16 *a0h, *a0l, *a1h, *a1l, *a2h, *a2l;
    __nv_bfloat16 *w0h, *w0l, *w1h, *w1l, *w2h, *w2l, *w3h, *w3l;
    __nv_bfloat16 *qh, *ql, *kh, *kl, *vh, *vl;
    cudaGetSymbolAddress((void**)&a0h, g_a0h); cudaGetSymbolAddress((void**)&a0l, g_a0l);
    cudaGetSymbolAddress((void**)&a1h, g_a1h); cudaGetSymbolAddress((void**)&a1l, g_a1l);
    cudaGetSymbolAddress((void**)&a2h, g_a2h); cudaGetSymbolAddress((void**)&a2l, g_a2l);
    cudaGetSymbolAddress((void**)&w0h, g_w0h); cudaGetSymbolAddress((void**)&w0l, g_w0l);
    cudaGetSymbolAddress((void**)&w1h, g_w1h); cudaGetSymbolAddress((void**)&w1l, g_w1l);
    cudaGetSymbolAddress((void**)&w2h, g_w2h); cudaGetSymbolAddress((void**)&w2l, g_w2l);
    cudaGetSymbolAddress((void**)&w3h, g_w3h); cudaGetSymbolAddress((void**)&w3l, g_w3l);
    cudaGetSymbolAddress((void**)&qh, g_qh);   cudaGetSymbolAddress((void**)&ql, g_ql);
    cudaGetSymbolAddress((void**)&kh, g_kh);   cudaGetSymbolAddress((void**)&kl, g_kl);
    cudaGetSymbolAddress((void**)&vh, g_vh);   cudaGetSymbolAddress((void**)&vl, g_vl);

    if ((long long)out_size >= (long long)OUT_ELEMS + ATTN_ELEMS) {
        attn = out + OUT_ELEMS;
    } else {
        cudaGetSymbolAddress((void**)&attn, g_attn_scratch);
    }

    cudaFuncSetAttribute(proj_qkv_kernel,
                         cudaFuncAttributeMaxDynamicSharedMemorySize, PROJ_DSMEM);
    cudaFuncSetAttribute(proj_out_kernel,
                         cudaFuncAttributeMaxDynamicSharedMemorySize, PROJ_DSMEM);
    cudaFuncSetAttribute(score_mma_kernel,
                         cudaFuncAttributeMaxDynamicSharedMemorySize, PROJ_DSMEM);

    detect_mask_kernel<<<1, 1>>>(mask);

    const int n4 = NM * ND / 4;                      // 1,048,576
    dim3 blk(256);

    // merged prep: all input splits + all weight transposes
    dim3 gsp(n4 / 256, 1, 3);
    split3_kernel<<<gsp, blk>>>(query, key, value,
                                a0h, a0l, a1h, a1l, a2h, a2l, n4);
    dim3 gtr(ND / 32, ND / 32, 4);
    transpose4_kernel<<<gtr, dim3(32, 8)>>>(Wq, Wk, Wv, Wo,
                                            w0h, w0l, w1h, w1l,
                                            w2h, w2l, w3h, w3l);

    // merged Q/K/V projections (gridDim.z = 3)
    dim3 gqkv(ND / 128, NM / 128, 3);                // (8, 32, 3) = 768 CTAs
    proj_qkv_kernel<<<gqkv, blk, PROJ_DSMEM>>>(
        a0h, a0l, a1h, a1l, a2h, a2l,
        w0h, w0l, w1h, w1l, w2h, w2l,
        bq, bk, bv, qh, ql, kh, kl, vh, vl);

    dim3 gscore(NS / 128, NS / 128, NBH);            // (16, 16, 32)
    score_mma_kernel<<<gscore, blk, PROJ_DSMEM>>>(qh, ql, kh, kl, mask, attn);

    softmax_kernel<<<NBH * NS, blk>>>(attn);

    dim3 gav(NS / 64, NBH);                          // (32, 32) = 1024 CTAs
    av_mma_kernel<<<gav, blk>>>(attn, vh, vl, a0h, a0l);  // split ctx -> a0h/a0l

    dim3 gout(ND / 128, NM / 128);                   // (8, 32)
    proj_out_kernel<<<gout, blk, PROJ_DSMEM>>>(a0h, a0l, w3h, w3l, bo, out);
}

// round 14
// speedup vs baseline: 1.0761x; 1.0761x over previous
#include <cuda_runtime.h>
#include <cuda_bf16.h>
#include <math.h>
#include <stdint.h>

// Problem constants
#define NB   2
#define NS   2048
#define ND   1024
#define NH   16
#define NHD  64
#define NBH  (NB*NH)       // 32
#define NM   (NB*NS)       // 4096
#define OUT_ELEMS  (NB*NS*ND)                        // 4,194,304
#define ATTN_ELEMS ((long long)NBH*(long long)NS*NS) // 134,217,728

#define NEG_INF __int_as_float(0xff800000)

// ---- scratch (device globals; no runtime allocation allowed) ----
__device__ float g_attn_scratch[134217728]; // fallback if out buffer excludes attn
__device__ int   g_mask_is_u8;
// bf16 split operands (separate buffers so Q/K/V pipelines are independent)
__device__ __nv_bfloat16 g_a0h[NM * ND], g_a0l[NM * ND];   // query split / ctx split
__device__ __nv_bfloat16 g_a1h[NM * ND], g_a1l[NM * ND];   // key split
__device__ __nv_bfloat16 g_a2h[NM * ND], g_a2l[NM * ND];   // value split
__device__ __nv_bfloat16 g_w0h[ND * ND], g_w0l[ND * ND];   // Wq^T
__device__ __nv_bfloat16 g_w1h[ND * ND], g_w1l[ND * ND];   // Wk^T
__device__ __nv_bfloat16 g_w2h[ND * ND], g_w2l[ND * ND];   // Wv^T
__device__ __nv_bfloat16 g_w3h[ND * ND], g_w3l[ND * ND];   // Wo^T
__device__ __nv_bfloat16 g_qh[NBH * NS * NHD], g_ql[NBH * NS * NHD];
__device__ __nv_bfloat16 g_kh[NBH * NS * NHD], g_kl[NBH * NS * NHD];
__device__ __nv_bfloat16 g_vh[NBH * NS * NHD], g_vl[NBH * NS * NHD];

// ---------------------------------------------------------------------------
__global__ void detect_mask_kernel(const unsigned char* __restrict__ m) {
    g_mask_is_u8 = (m[1] != 0) ? 1 : 0;
}

// ---------------------------------------------------------------------------
// helpers
// ---------------------------------------------------------------------------
__device__ __forceinline__ void split2(float x0, float x1,
                                       unsigned& hi, unsigned& lo) {
    __nv_bfloat16 h0 = __float2bfloat16(x0);
    __nv_bfloat16 h1 = __float2bfloat16(x1);
    __nv_bfloat162 hp = __halves2bfloat162(h0, h1);
    hi = *reinterpret_cast<unsigned*>(&hp);
    float l0 = x0 - __bfloat162float(h0);
    float l1 = x1 - __bfloat162float(h1);
    __nv_bfloat162 lp = __floats2bfloat162_rn(l0, l1);
    lo = *reinterpret_cast<unsigned*>(&lp);
}

__device__ __forceinline__ void mma16(float* c, const unsigned* a, const unsigned* b) {
    asm volatile(
        "mma.sync.aligned.m16n8k16.row.col.f32.bf16.bf16.f32 "
        "{%0,%1,%2,%3}, {%4,%5,%6,%7}, {%8,%9}, {%0,%1,%2,%3};"
        : "+f"(c[0]), "+f"(c[1]), "+f"(c[2]), "+f"(c[3])
        : "r"(a[0]), "r"(a[1]), "r"(a[2]), "r"(a[3]), "r"(b[0]), "r"(b[1]));
}

__device__ __forceinline__ uint32_t smem_u32(const void* p) {
    uint32_t a;
    asm("{ .reg .u64 t; cvta.to.shared.u64 t, %1; cvt.u32.u64 %0, t; }"
        : "=r"(a) : "l"(p));
    return a;
}

__device__ __forceinline__ void ldsm_x4(unsigned& r0, unsigned& r1,
                                        unsigned& r2, unsigned& r3, uint32_t a) {
    asm volatile("ldmatrix.sync.aligned.m8n8.x4.shared.b16 {%0,%1,%2,%3}, [%4];"
                 : "=r"(r0), "=r"(r1), "=r"(r2), "=r"(r3) : "r"(a));
}
__device__ __forceinline__ void ldsm_x4_t(unsigned& r0, unsigned& r1,
                                          unsigned& r2, unsigned& r3, uint32_t a) {
    asm volatile("ldmatrix.sync.aligned.m8n8.x4.trans.shared.b16 {%0,%1,%2,%3}, [%4];"
                 : "=r"(r0), "=r"(r1), "=r"(r2), "=r"(r3) : "r"(a));
}

__device__ __forceinline__ void cp16(uint32_t dst, const void* src) {
    asm volatile("cp.async.cg.shared.global [%0], [%1], 16;"
                 :: "r"(dst), "l"(src));
}
#define CP_COMMIT() asm volatile("cp.async.commit_group;" ::: "memory")
#define CP_WAIT1()  asm volatile("cp.async.wait_group 1;" ::: "memory")
#define CP_WAIT0()  asm volatile("cp.async.wait_group 0;" ::: "memory")

// ---------------------------------------------------------------------------
// Prep kernels — merged across the 3 inputs / 4 weights (blockIdx.z selects)
// ---------------------------------------------------------------------------
__global__ void split3_kernel(const float* __restrict__ X0,
                              const float* __restrict__ X1,
                              const float* __restrict__ X2,
                              __nv_bfloat16* __restrict__ H0, __nv_bfloat16* __restrict__ L0,
                              __nv_bfloat16* __restrict__ H1, __nv_bfloat16* __restrict__ L1,
                              __nv_bfloat16* __restrict__ H2, __nv_bfloat16* __restrict__ L2,
                              int n4)
{
    int idx = blockIdx.x * blockDim.x + threadIdx.x;
    if (idx >= n4) return;
    const int z = blockIdx.z;
    const float* X = (z == 0) ? X0 : (z == 1) ? X1 : X2;
    __nv_bfloat16* hi = (z == 0) ? H0 : (z == 1) ? H1 : H2;
    __nv_bfloat16* lo = (z == 0) ? L0 : (z == 1) ? L1 : L2;
    float4 v = ((const float4*)X)[idx];
    unsigned h01, l01, h23, l23;
    split2(v.x, v.y, h01, l01);
    split2(v.z, v.w, h23, l23);
    ((uint2*)hi)[idx] = make_uint2(h01, h23);
    ((uint2*)lo)[idx] = make_uint2(l01, l23);
}

__global__ void transpose4_kernel(const float* __restrict__ W0,
                                  const float* __restrict__ W1,
                                  const float* __restrict__ W2,
                                  const float* __restrict__ W3,
                                  __nv_bfloat16* __restrict__ T0h, __nv_bfloat16* __restrict__ T0l,
                                  __nv_bfloat16* __restrict__ T1h, __nv_bfloat16* __restrict__ T1l,
                                  __nv_bfloat16* __restrict__ T2h, __nv_bfloat16* __restrict__ T2l,
                                  __nv_bfloat16* __restrict__ T3h, __nv_bfloat16* __restrict__ T3l)
{
    __shared__ float ts[32][33];
    const int z = blockIdx.z;
    const float* W = (z == 0) ? W0 : (z == 1) ? W1 : (z == 2) ? W2 : W3;
    __nv_bfloat16* Th = (z == 0) ? T0h : (z == 1) ? T1h : (z == 2) ? T2h : T3h;
    __nv_bfloat16* Tl = (z == 0) ? T0l : (z == 1) ? T1l : (z == 2) ? T2l : T3l;

    int n0 = blockIdx.x * 32, k0 = blockIdx.y * 32;
    int tx = threadIdx.x, ty = threadIdx.y;  // (32, 8)
    #pragma unroll
    for (int i = 0; i < 4; i++)
        ts[ty * 4 + i][tx] = W[(size_t)(k0 + ty * 4 + i) * ND + n0 + tx];
    __syncthreads();
    #pragma unroll
    for (int i = 0; i < 4; i++) {
        int nl = ty * 4 + i;
        float v = ts[tx][nl];
        __nv_bfloat16 h = __float2bfloat16(v);
        float l = v - __bfloat162float(h);
        size_t o = (size_t)(n0 + nl) * ND + k0 + tx;
        Th[o] = h;
        Tl[o] = __float2bfloat16(l);
    }
}

// ---------------------------------------------------------------------------
// Projection GEMM core (device inline). cp.async 2-stage ring, one barrier
// per k-tile. 128x128 block, ktile 32, 8 warps (2m x 4n), 3xBF16.
// ---------------------------------------------------------------------------
#define PITCH 80
#define TILE_B (128 * PITCH)      // 10240
#define STG    (4 * TILE_B)       // 40960 per stage
#define PROJ_DSMEM (2 * STG)      // 81920

__device__ __forceinline__ void proj_core(
    char* sm,
    const __nv_bfloat16* __restrict__ Ahi, const __nv_bfloat16* __restrict__ Alo,
    const __nv_bfloat16* __restrict__ Bhi, const __nv_bfloat16* __restrict__ Blo,
    const float* __restrict__ bias,
    float* __restrict__ Cf,
    __nv_bfloat16* __restrict__ Chi, __nv_bfloat16* __restrict__ Clo,
    int mode, int row0, int col0)
{
    const int tid  = threadIdx.x;
    const int warp = tid >> 5, lane = tid & 31;
    const int gid  = lane >> 2, tig = lane & 3;
    const int wm   = (warp & 1) * 64;
    const int wn   = (warp >> 1) * 32;

    const uint32_t sb = smem_u32(sm);
    const int q = lane >> 3, rr = lane & 7;
    const uint32_t aOff = (uint32_t)((wm + (q & 1) * 8 + rr) * PITCH + (q >> 1) * 16);
    const uint32_t bOff = 2u * TILE_B +
                          (uint32_t)((wn + (q >> 1) * 8 + rr) * PITCH + (q & 1) * 16);
    const int cr0 = tid >> 2,           cc0 = tid & 3;
    const int cr1 = (256 + tid) >> 2,   cc1 = (256 + tid) & 3;

    float acc[4][4][4] = {};

    #define PJ_ISSUE(stage, k0v) do {                                            \
        const uint32_t stg_ = sb + (uint32_t)((stage) * STG);                    \
        uint32_t d0 = stg_ + (uint32_t)(cr0 * PITCH + cc0 * 16);                 \
        size_t ga0 = (size_t)(row0 + cr0) * ND + (k0v) + cc0 * 8;                \
        size_t gb0 = (size_t)(col0 + cr0) * ND + (k0v) + cc0 * 8;                \
        cp16(d0, Ahi + ga0);              cp16(d0 + TILE_B, Alo + ga0);          \
        cp16(d0 + 2*TILE_B, Bhi + gb0);   cp16(d0 + 3*TILE_B, Blo + gb0);        \
        uint32_t d1 = stg_ + (uint32_t)(cr1 * PITCH + cc1 * 16);                 \
        size_t ga1 = (size_t)(row0 + cr1) * ND + (k0v) + cc1 * 8;                \
        size_t gb1 = (size_t)(col0 + cr1) * ND + (k0v) + cc1 * 8;                \
        cp16(d1, Ahi + ga1);              cp16(d1 + TILE_B, Alo + ga1);          \
        cp16(d1 + 2*TILE_B, Bhi + gb1);   cp16(d1 + 3*TILE_B, Blo + gb1);        \
        CP_COMMIT();                                                             \
    } while (0)

    PJ_ISSUE(0, 0);

    #pragma unroll 1
    for (int kt = 0; kt < 32; kt++) {
        CP_WAIT0();
        __syncthreads();
        if (kt + 1 < 32)
            PJ_ISSUE((kt + 1) & 1, (kt + 1) * 32);

        const uint32_t stb = sb + (uint32_t)((kt & 1) * STG);
        const uint32_t aA = stb + aOff, bA = stb + bOff;

        #pragma unroll
        for (int ks = 0; ks < 2; ks++) {
            const uint32_t kb = ks * 32;
            unsigned ah[4][4], al[4][4], bx[4][2];
            #pragma unroll
            for (int mt = 0; mt < 4; mt++)
                ldsm_x4(ah[mt][0], ah[mt][1], ah[mt][2], ah[mt][3],
                        aA + mt * 16 * PITCH + kb);
            #pragma unroll
            for (int n2 = 0; n2 < 2; n2++)
                ldsm_x4(bx[n2*2][0], bx[n2*2][1], bx[n2*2+1][0], bx[n2*2+1][1],
                        bA + n2 * 16 * PITCH + kb);
            #pragma unroll
            for (int mt = 0; mt < 4; mt++)
                #pragma unroll
                for (int nt = 0; nt < 4; nt++)
                    mma16(acc[mt][nt], ah[mt], bx[nt]);     // hi*hi
            #pragma unroll
            for (int mt = 0; mt < 4; mt++)
                ldsm_x4(al[mt][0], al[mt][1], al[mt][2], al[mt][3],
                        aA + TILE_B + mt * 16 * PITCH + kb);
            #pragma unroll
            for (int mt = 0; mt < 4; mt++)
                #pragma unroll
                for (int nt = 0; nt < 4; nt++)
                    mma16(acc[mt][nt], al[mt], bx[nt]);     // lo*hi
            #pragma unroll
            for (int n2 = 0; n2 < 2; n2++)
                ldsm_x4(bx[n2*2][0], bx[n2*2][1], bx[n2*2+1][0], bx[n2*2+1][1],
                        bA + TILE_B + n2 * 16 * PITCH + kb);
            #pragma unroll
            for (int mt = 0; mt < 4; mt++)
                #pragma unroll
                for (int nt = 0; nt < 4; nt++)
                    mma16(acc[mt][nt], ah[mt], bx[nt]);     // hi*lo
        }
    }

    #pragma unroll
    for (int mt = 0; mt < 4; mt++) {
        #pragma unroll
        for (int nt = 0; nt < 4; nt++) {
            int n = col0 + wn + nt * 8 + tig * 2;
            float b0 = bias[n], b1 = bias[n + 1];
            #pragma unroll
            for (int h2 = 0; h2 < 2; h2++) {
                int m = row0 + wm + mt * 16 + gid + h2 * 8;
                float c0 = acc[mt][nt][h2 * 2]     + b0;
                float c1 = acc[mt][nt][h2 * 2 + 1] + b1;
                if (mode == 1) {
                    int b = m >> 11, s = m & (NS - 1), hh = n >> 6, d = n & 63;
                    size_t o = (((size_t)(b * NH + hh)) * NS + s) * NHD + d;
                    unsigned hv, lv;
                    split2(c0, c1, hv, lv);
                    *(unsigned*)&Chi[o] = hv;
                    *(unsigned*)&Clo[o] = lv;
                } else {
                    *(float2*)&Cf[(size_t)m * ND + n] = make_float2(c0, c1);
                }
            }
        }
    }
    #undef PJ_ISSUE
}

// merged QKV projection: gridDim.z = 3 selects the pipeline
__global__ void __launch_bounds__(256, 2)
proj_qkv_kernel(const __nv_bfloat16* __restrict__ A0h, const __nv_bfloat16* __restrict__ A0l,
                const __nv_bfloat16* __restrict__ A1h, const __nv_bfloat16* __restrict__ A1l,
                const __nv_bfloat16* __restrict__ A2h, const __nv_bfloat16* __restrict__ A2l,
                const __nv_bfloat16* __restrict__ B0h, const __nv_bfloat16* __restrict__ B0l,
                const __nv_bfloat16* __restrict__ B1h, const __nv_bfloat16* __restrict__ B1l,
                const __nv_bfloat16* __restrict__ B2h, const __nv_bfloat16* __restrict__ B2l,
                const float* __restrict__ bq, const float* __restrict__ bk,
                const float* __restrict__ bv,
                __nv_bfloat16* __restrict__ qh, __nv_bfloat16* __restrict__ ql,
                __nv_bfloat16* __restrict__ kh, __nv_bfloat16* __restrict__ kl,
                __nv_bfloat16* __restrict__ vh, __nv_bfloat16* __restrict__ vl)
{
    extern __shared__ __align__(16) char sm[];
    const int z = blockIdx.z;
    const __nv_bfloat16* Ahi = (z == 0) ? A0h : (z == 1) ? A1h : A2h;
    const __nv_bfloat16* Alo = (z == 0) ? A0l : (z == 1) ? A1l : A2l;
    const __nv_bfloat16* Bhi = (z == 0) ? B0h : (z == 1) ? B1h : B2h;
    const __nv_bfloat16* Blo = (z == 0) ? B0l : (z == 1) ? B1l : B2l;
    const float* bias = (z == 0) ? bq : (z == 1) ? bk : bv;
    __nv_bfloat16* Chi = (z == 0) ? qh : (z == 1) ? kh : vh;
    __nv_bfloat16* Clo = (z == 0) ? ql : (z == 1) ? kl : vl;
    proj_core(sm, Ahi, Alo, Bhi, Blo, bias, nullptr, Chi, Clo, 1,
              blockIdx.y * 128, blockIdx.x * 128);
}

// output projection (fp32 out)
__global__ void __launch_bounds__(256, 2)
proj_out_kernel(const __nv_bfloat16* __restrict__ Ahi, const __nv_bfloat16* __restrict__ Alo,
                const __nv_bfloat16* __restrict__ Bhi, const __nv_bfloat16* __restrict__ Blo,
                const float* __restrict__ bias, float* __restrict__ Cf)
{
    extern __shared__ __align__(16) char sm[];
    proj_core(sm, Ahi, Alo, Bhi, Blo, bias, Cf, nullptr, nullptr, 0,
              blockIdx.y * 128, blockIdx.x * 128);
}

// ---------------------------------------------------------------------------
// Scores (R12 proven): attn = mask ? (Q.K)*scale : -inf. Streaming stores for
// the write-once attn tensor (537 MB cannot live in L2).
// grid = (kt=16, qt=16, bh=32)
// ---------------------------------------------------------------------------
__global__ void __launch_bounds__(256, 2)
score_mma_kernel(const __nv_bfloat16* __restrict__ qh_g,
                 const __nv_bfloat16* __restrict__ ql_g,
                 const __nv_bfloat16* __restrict__ kh_g,
                 const __nv_bfloat16* __restrict__ kl_g,
                 const unsigned char* __restrict__ mask8,
                 float* __restrict__ attn)
{
    extern __shared__ __align__(16) char sm[];

    const int tid  = threadIdx.x;
    const int warp = tid >> 5, lane = tid & 31;
    const int gid  = lane >> 2, tig = lane & 3;
    const int wm   = (warp & 1) * 64;
    const int wn   = (warp >> 1) * 32;
    const int kt = blockIdx.x, qt = blockIdx.y, bh_i = blockIdx.z;

    const size_t hb = (size_t)bh_i * NS * NHD;
    const uint32_t sb = smem_u32(sm);
    const int q = lane >> 3, rr = lane & 7;
    const uint32_t aOff = (uint32_t)((wm + (q & 1) * 8 + rr) * PITCH + (q >> 1) * 16);
    const uint32_t bOff = 2u * TILE_B +
                          (uint32_t)((wn + (q >> 1) * 8 + rr) * PITCH + (q & 1) * 16);
    const int cr0 = tid >> 2,         cc0 = tid & 3;
    const int cr1 = (256 + tid) >> 2, cc1 = (256 + tid) & 3;

    float acc[4][4][4] = {};

    #define SC_ISSUE(stage, d0v)  do {                                          \
        const uint32_t stg_ = sb + (uint32_t)((stage) * STG);                   \
        uint32_t da0 = stg_ + (uint32_t)(cr0 * PITCH + cc0 * 16);               \
        size_t gq0 = hb + (size_t)(qt * 128 + cr0) * NHD + (d0v) + cc0 * 8;     \
        size_t gk0 = hb + (size_t)(kt * 128 + cr0) * NHD + (d0v) + cc0 * 8;     \
        cp16(da0, qh_g + gq0);             cp16(da0 + TILE_B, ql_g + gq0);      \
        cp16(da0 + 2*TILE_B, kh_g + gk0);  cp16(da0 + 3*TILE_B, kl_g + gk0);    \
        uint32_t da1 = stg_ + (uint32_t)(cr1 * PITCH + cc1 * 16);               \
        size_t gq1 = hb + (size_t)(qt * 128 + cr1) * NHD + (d0v) + cc1 * 8;     \
        size_t gk1 = hb + (size_t)(kt * 128 + cr1) * NHD + (d0v) + cc1 * 8;     \
        cp16(da1, qh_g + gq1);             cp16(da1 + TILE_B, ql_g + gq1);      \
        cp16(da1 + 2*TILE_B, kh_g + gk1);  cp16(da1 + 3*TILE_B, kl_g + gk1);    \
        CP_COMMIT();                                                            \
    } while (0)

    SC_ISSUE(0, 0);

    #pragma unroll
    for (int dt = 0; dt < 2; dt++) {
        CP_WAIT0();
        __syncthreads();
        if (dt + 1 < 2) SC_ISSUE(1, 32);

        const uint32_t stb = sb + (uint32_t)((dt & 1) * STG);
        const uint32_t aA = stb + aOff, bA = stb + bOff;

        #pragma unroll
        for (int ks = 0; ks < 2; ks++) {
            const uint32_t kb = ks * 32;
            unsigned ah[4][4], al[4][4], bx[4][2];
            #pragma unroll
            for (int mt = 0; mt < 4; mt++)
                ldsm_x4(ah[mt][0], ah[mt][1], ah[mt][2], ah[mt][3],
                        aA + mt * 16 * PITCH + kb);
            #pragma unroll
            for (int n2 = 0; n2 < 2; n2++)
                ldsm_x4(bx[n2*2][0], bx[n2*2][1], bx[n2*2+1][0], bx[n2*2+1][1],
                        bA + n2 * 16 * PITCH + kb);
            #pragma unroll
            for (int mt = 0; mt < 4; mt++)
                #pragma unroll
                for (int nt = 0; nt < 4; nt++)
                    mma16(acc[mt][nt], ah[mt], bx[nt]);
            #pragma unroll
            for (int mt = 0; mt < 4; mt++)
                ldsm_x4(al[mt][0], al[mt][1], al[mt][2], al[mt][3],
                        aA + TILE_B + mt * 16 * PITCH + kb);
            #pragma unroll
            for (int mt = 0; mt < 4; mt++)
                #pragma unroll
                for (int nt = 0; nt < 4; nt++)
                    mma16(acc[mt][nt], al[mt], bx[nt]);
            #pragma unroll
            for (int n2 = 0; n2 < 2; n2++)
                ldsm_x4(bx[n2*2][0], bx[n2*2][1], bx[n2*2+1][0], bx[n2*2+1][1],
                        bA + TILE_B + n2 * 16 * PITCH + kb);
            #pragma unroll
            for (int mt = 0; mt < 4; mt++)
                #pragma unroll
                for (int nt = 0; nt < 4; nt++)
                    mma16(acc[mt][nt], ah[mt], bx[nt]);
        }
    }

    const float scale = 0.125f;
    const int use8 = g_mask_is_u8;
    const int* mask32 = (const int*)mask8;

    #pragma unroll
    for (int mt = 0; mt < 4; mt++) {
        #pragma unroll
        for (int nt = 0; nt < 4; nt++) {
            int n = kt * 128 + wn + nt * 8 + tig * 2;
            #pragma unroll
            for (int h2 = 0; h2 < 2; h2++) {
                int m = qt * 128 + wm + mt * 16 + gid + h2 * 8;
                float c0 = acc[mt][nt][h2 * 2]     * scale;
                float c1 = acc[mt][nt][h2 * 2 + 1] * scale;
                bool m0, m1;
                if (use8) {
                    uchar2 mv = *(const uchar2*)&mask8[(size_t)m * NS + n];
                    m0 = mv.x != 0; m1 = mv.y != 0;
                } else {
                    int2 mv = *(const int2*)&mask32[(size_t)m * NS + n];
                    m0 = mv.x != 0; m1 = mv.y != 0;
                }
                float2 o = make_float2(m0 ? c0 : NEG_INF, m1 ? c1 : NEG_INF);
                __stcs((float2*)&attn[((size_t)bh_i * NS + m) * NS + n], o);
            }
        }
    }
}

// ---------------------------------------------------------------------------
// Row softmax over 2048 elements, in place. (R8 proven)
// ---------------------------------------------------------------------------
__global__ void softmax_kernel(float* __restrict__ attn)
{
    const size_t row = blockIdx.x;
    float* p = attn + row * (size_t)NS;
    const int tid = threadIdx.x;

    float v[8];
    float mx = NEG_INF;
    #pragma unroll
    for (int i = 0; i < 8; i++) {
        v[i] = p[tid + i * 256];
        mx = fmaxf(mx, v[i]);
    }

    __shared__ float sh[8];
    #pragma unroll
    for (int o = 16; o > 0; o >>= 1)
        mx = fmaxf(mx, __shfl_xor_sync(0xffffffffu, mx, o));
    if ((tid & 31) == 0) sh[tid >> 5] = mx;
    __syncthreads();
    if (tid < 32) {
        float m2 = (tid < 8) ? sh[tid] : NEG_INF;
        #pragma unroll
        for (int o = 4; o > 0; o >>= 1)
            m2 = fmaxf(m2, __shfl_xor_sync(0xffffffffu, m2, o));
        if (tid == 0) sh[0] = m2;
    }
    __syncthreads();
    mx = sh[0];
    __syncthreads();

    float s = 0.0f;
    #pragma unroll
    for (int i = 0; i < 8; i++) {
        v[i] = __expf(v[i] - mx);
        s += v[i];
    }
    #pragma unroll
    for (int o = 16; o > 0; o >>= 1)
        s += __shfl_xor_sync(0xffffffffu, s, o);
    if ((tid & 31) == 0) sh[tid >> 5] = s;
    __syncthreads();
    if (tid < 32) {
        float s2 = (tid < 8) ? sh[tid] : 0.0f;
        #pragma unroll
        for (int o = 4; o > 0; o >>= 1)
            s2 += __shfl_xor_sync(0xffffffffu, s2, o);
        if (tid == 0) sh[0] = s2;
    }
    __syncthreads();
    const float inv = 1.0f / sh[0];

    #pragma unroll
    for (int i = 0; i < 8; i++)
        p[tid + i * 256] = v[i] * inv;
}

// ---------------------------------------------------------------------------
// PV (R12 proven shape): 128(q) x 64(d) block tile, ktile 32, 8 warps (4m x 2n).
// P reg-prefetch (ldcs: read-once) + inline split; V cp.async ring.
// ctx stores streaming (no reuse before out-proj). grid = (qt=16, bh=32)
// ---------------------------------------------------------------------------
#define VPITCH 144
#define VTILE_B (32 * VPITCH)      // 4608
#define VSTG    (2 * VTILE_B)      // 9216 (hi+lo)
#define VBASE   (2 * TILE_B)       // after Ph, Pl

__global__ void __launch_bounds__(256, 2)
av_mma_kernel(const float* __restrict__ attn,
              const __nv_bfloat16* __restrict__ vh_g,
              const __nv_bfloat16* __restrict__ vl_g,
              __nv_bfloat16* __restrict__ Chi,
              __nv_bfloat16* __restrict__ Clo)
{
    __shared__ __align__(16) char sm[VBASE + 2 * VSTG];  // Ph | Pl | Vstg0 | Vstg1

    const int tid  = threadIdx.x;
    const int warp = tid >> 5, lane = tid & 31;
    const int gid  = lane >> 2, tig = lane & 3;
    const int wm   = (warp & 3) * 32;
    const int wn   = (warp >> 2) * 32;
    const int qt = blockIdx.x, bh_i = blockIdx.y;

    const size_t hb = (size_t)bh_i * NS * NHD;
    const float* prow = attn + ((size_t)bh_i * NS + qt * 128) * NS;

    const uint32_t sb = smem_u32(sm);
    const int q = lane >> 3, rr = lane & 7;
    const uint32_t aAddr = sb + (uint32_t)((wm + (q & 1) * 8 + rr) * PITCH + (q >> 1) * 16);
    const uint32_t vOff  = (uint32_t)(((q & 1) * 8 + rr) * VPITCH + (wn + (q >> 1) * 8) * 2);
    const int vr = tid >> 3, vc = tid & 7;

    float acc[2][4][4] = {};
    float4 pr[4];

    // prologue: V stage 0 + P regs tile 0
    {
        size_t gv = hb + (size_t)vr * NHD + vc * 8;
        uint32_t d = sb + VBASE + (uint32_t)(vr * VPITCH + vc * 16);
        cp16(d, vh_g + gv);
        cp16(d + VTILE_B, vl_g + gv);
        CP_COMMIT();
        #pragma unroll
        for (int i = 0; i < 4; i++) {
            int idx = i * 256 + tid;
            int r = idx >> 3, c4 = idx & 7;
            pr[i] = __ldcs((const float4*)&prow[(size_t)r * NS + c4 * 4]);
        }
    }

    #pragma unroll 1
    for (int kt = 0; kt < 64; kt++) {
        if (kt + 1 < 64) {
            size_t gv = hb + (size_t)((kt + 1) * 32 + vr) * NHD + vc * 8;
            uint32_t d = sb + VBASE + (uint32_t)(((kt + 1) & 1) * VSTG + vr * VPITCH + vc * 16);
            cp16(d, vh_g + gv);
            cp16(d + VTILE_B, vl_g + gv);
            CP_COMMIT();
        }
        // STS P from regs (split inline)
        #pragma unroll
        for (int i = 0; i < 4; i++) {
            int idx = i * 256 + tid;
            int r = idx >> 3, c4 = idx & 7;
            unsigned h01, l01, h23, l23;
            split2(pr[i].x, pr[i].y, h01, l01);
            split2(pr[i].z, pr[i].w, h23, l23);
            uint32_t da = (uint32_t)(r * PITCH + c4 * 8);
            *(uint2*)(sm + da)          = make_uint2(h01, h23);
            *(uint2*)(sm + TILE_B + da) = make_uint2(l01, l23);
        }
        // prefetch next P tile into regs (lands during mma)
        if (kt + 1 < 64) {
            const int k0n = (kt + 1) * 32;
            #pragma unroll
            for (int i = 0; i < 4; i++) {
                int idx = i * 256 + tid;
                int r = idx >> 3, c4 = idx & 7;
                pr[i] = __ldcs((const float4*)&prow[(size_t)r * NS + k0n + c4 * 4]);
            }
            CP_WAIT1();
        } else {
            CP_WAIT0();
        }
        __syncthreads();

        const uint32_t vA = sb + VBASE + (uint32_t)((kt & 1) * VSTG) + vOff;

        #pragma unroll
        for (int ks = 0; ks < 2; ks++) {
            const uint32_t kb  = ks * 32;
            const uint32_t vkb = ks * 16 * VPITCH;
            unsigned ah[2][4], al[2][4], bx[4][2];
            #pragma unroll
            for (int mt = 0; mt < 2; mt++)
                ldsm_x4(ah[mt][0], ah[mt][1], ah[mt][2], ah[mt][3],
                        aAddr + mt * 16 * PITCH + kb);
            #pragma unroll
            for (int n2 = 0; n2 < 2; n2++)
                ldsm_x4_t(bx[n2*2][0], bx[n2*2][1], bx[n2*2+1][0], bx[n2*2+1][1],
                          vA + vkb + n2 * 32);
            #pragma unroll
            for (int mt = 0; mt < 2; mt++)
                #pragma unroll
                for (int nt = 0; nt < 4; nt++)
                    mma16(acc[mt][nt], ah[mt], bx[nt]);
            #pragma unroll
            for (int mt = 0; mt < 2; mt++)
                ldsm_x4(al[mt][0], al[mt][1], al[mt][2], al[mt][3],
                        aAddr + TILE_B + mt * 16 * PITCH + kb);
            #pragma unroll
            for (int mt = 0; mt < 2; mt++)
                #pragma unroll
                for (int nt = 0; nt < 4; nt++)
                    mma16(acc[mt][nt], al[mt], bx[nt]);
            #pragma unroll
            for (int n2 = 0; n2 < 2; n2++)
                ldsm_x4_t(bx[n2*2][0], bx[n2*2][1], bx[n2*2+1][0], bx[n2*2+1][1],
                          vA + VTILE_B + vkb + n2 * 32);
            #pragma unroll
            for (int mt = 0; mt < 2; mt++)
                #pragma unroll
                for (int nt = 0; nt < 4; nt++)
                    mma16(acc[mt][nt], ah[mt], bx[nt]);
        }
        __syncthreads();
    }

    // epilogue: split ctx, streaming-write to out-proj A buffers
    const int b = bh_i >> 4, h = bh_i & 15;
    #pragma unroll
    for (int mt = 0; mt < 2; mt++) {
        #pragma unroll
        for (int nt = 0; nt < 4; nt++) {
            int n = wn + nt * 8 + tig * 2;
            #pragma unroll
            for (int h2 = 0; h2 < 2; h2++) {
                int s = qt * 128 + wm + mt * 16 + gid + h2 * 8;
                unsigned hv, lv;
                split2(acc[mt][nt][h2 * 2], acc[mt][nt][h2 * 2 + 1], hv, lv);
                size_t o = (size_t)(b * NS + s) * ND + h * NHD + n;
                __stcs((unsigned*)&Chi[o], hv);
                __stcs((unsigned*)&Clo[o], lv);
            }
        }
    }
}

// ---------------------------------------------------------------------------
extern "C" void kernel_launch(void* const* d_in, const int* in_sizes, int n_in,
                              void* d_out, int out_size)
{
    (void)in_sizes; (void)n_in;

    const float* query = (const float*)d_in[0];
    const float* key   = (const float*)d_in[1];
    const float* value = (const float*)d_in[2];
    const float* Wq    = (const float*)d_in[3];
    const float* bq    = (const float*)d_in[4];
    const float* Wk    = (const float*)d_in[5];
    const float* bk    = (const float*)d_in[6];
    const float* Wv    = (const float*)d_in[7];
    const float* bv    = (const float*)d_in[8];
    const float* Wo    = (const float*)d_in[9];
    const float* bo    = (const float*)d_in[10];
    const unsigned char* mask = (const unsigned char*)d_in[11];

    float* out = (float*)d_out;

    float* attn;
    __nv_bfloat16 *a0h, *a0l, *a1h, *a1l, *a2h, *a2l;
    __nv_bfloat16 *w0h, *w0l, *w1h, *w1l, *w2h, *w2l, *w3h, *w3l;
    __nv_bfloat16 *qh, *ql, *kh, *kl, *vh, *vl;
    cudaGetSymbolAddress((void**)&a0h, g_a0h); cudaGetSymbolAddress((void**)&a0l, g_a0l);
    cudaGetSymbolAddress((void**)&a1h, g_a1h); cudaGetSymbolAddress((void**)&a1l, g_a1l);
    cudaGetSymbolAddress((void**)&a2h, g_a2h); cudaGetSymbolAddress((void**)&a2l, g_a2l);
    cudaGetSymbolAddress((void**)&w0h, g_w0h); cudaGetSymbolAddress((void**)&w0l, g_w0l);
    cudaGetSymbolAddress((void**)&w1h, g_w1h); cudaGetSymbolAddress((void**)&w1l, g_w1l);
    cudaGetSymbolAddress((void**)&w2h, g_w2h); cudaGetSymbolAddress((void**)&w2l, g_w2l);
    cudaGetSymbolAddress((void**)&w3h, g_w3h); cudaGetSymbolAddress((void**)&w3l, g_w3l);
    cudaGetSymbolAddress((void**)&qh, g_qh);   cudaGetSymbolAddress((void**)&ql, g_ql);
    cudaGetSymbolAddress((void**)&kh, g_kh);   cudaGetSymbolAddress((void**)&kl, g_kl);
    cudaGetSymbolAddress((void**)&vh, g_vh);   cudaGetSymbolAddress((void**)&vl, g_vl);

    if ((long long)out_size >= (long long)OUT_ELEMS + ATTN_ELEMS) {
        attn = out + OUT_ELEMS;
    } else {
        cudaGetSymbolAddress((void**)&attn, g_attn_scratch);
    }

    cudaFuncSetAttribute(proj_qkv_kernel,
                         cudaFuncAttributeMaxDynamicSharedMemorySize, PROJ_DSMEM);
    cudaFuncSetAttribute(proj_out_kernel,
                         cudaFuncAttributeMaxDynamicSharedMemorySize, PROJ_DSMEM);
    cudaFuncSetAttribute(score_mma_kernel,
                         cudaFuncAttributeMaxDynamicSharedMemorySize, PROJ_DSMEM);

    detect_mask_kernel<<<1, 1>>>(mask);

    const int n4 = NM * ND / 4;                      // 1,048,576
    dim3 blk(256);

    // merged prep: all input splits + all weight transposes
    dim3 gsp(n4 / 256, 1, 3);
    split3_kernel<<<gsp, blk>>>(query, key, value,
                                a0h, a0l, a1h, a1l, a2h, a2l, n4);
    dim3 gtr(ND / 32, ND / 32, 4);
    transpose4_kernel<<<gtr, dim3(32, 8)>>>(Wq, Wk, Wv, Wo,
                                            w0h, w0l, w1h, w1l,
                                            w2h, w2l, w3h, w3l);

    // merged Q/K/V projections (gridDim.z = 3)
    dim3 gqkv(ND / 128, NM / 128, 3);                // (8, 32, 3) = 768 CTAs
    proj_qkv_kernel<<<gqkv, blk, PROJ_DSMEM>>>(
        a0h, a0l, a1h, a1l, a2h, a2l,
        w0h, w0l, w1h, w1l, w2h, w2l,
        bq, bk, bv, qh, ql, kh, kl, vh, vl);

    dim3 gscore(NS / 128, NS / 128, NBH);            // (16, 16, 32)
    score_mma_kernel<<<gscore, blk, PROJ_DSMEM>>>(qh, ql, kh, kl, mask, attn);

    softmax_kernel<<<NBH * NS, blk>>>(attn);

    dim3 gav(NS / 128, NBH);                         // (16, 32)
    av_mma_kernel<<<gav, blk>>>(attn, vh, vl, a0h, a0l);  // split ctx -> a0h/a0l

    dim3 gout(ND / 128, NM / 128);                   // (8, 32)
    proj_out_kernel<<<gout, blk, PROJ_DSMEM>>>(a0h, a0l, w3h, w3l, bo, out);
}